// round 14
// baseline (speedup 1.0000x reference)
#include <cuda_runtime.h>
#include <cuda_fp16.h>
#include <cstdint>

#define SS   1024
#define HH   512
#define WW   512
#define BB   32
#define NTHREADS 256
#define F4_PER_ROUND 4
#define NROUNDS 2
#define F4_PER_BLOCK (NTHREADS * F4_PER_ROUND * NROUNDS)  // 2048
#define F4_PER_IMG   (HH*WW*3/4)                          // 196608
#define BLOCKS_X     (F4_PER_IMG / F4_PER_BLOCK)          // 96

__global__ __launch_bounds__(NTHREADS, 8)
void gridmask_kernel(const float* __restrict__ img,
                     const float* __restrict__ angles,
                     const int*   __restrict__ gridblock,
                     const int*   __restrict__ start1,
                     const int*   __restrict__ start2,
                     float*       __restrict__ out) {
    // fp16 paired stripe LUTs stored as raw half2 bits:
    //   s_lut[i]      = (rowstripe(i), rowstripe(i+1))
    //   s_lut[SS + i] = (colstripe(i), colstripe(i+1))
    __shared__ uint32_t s_lut[2 * SS];   // 8 KB
    __shared__ float    s_trig[2];

    const int b = blockIdx.y;

    // ---- Branchless int-packed LUT build ----
    // stripe(d) over a 5-run: v = (d>=0) & (d<lim) & ((t<length)|(t>=gb)),
    // t = rem0+k. Valid because length>=91>4 and gb>=153>4.
    {
        const int gb  = gridblock[b];
        const int st1 = start1[b];
        const int st2 = start2[b];
        float lf = __fadd_rn(__fmul_rn((float)gb, 0.6f), 0.5f);
        int length = (int)lf;
        length = min(max(length, 1), gb - 1);
        const unsigned M = (1u << 22) / (unsigned)gb + 1u;
        const int lim = (int)((((unsigned)SS * M) >> 22) * (unsigned)gb);
        const int i0 = threadIdx.x * 4;

        auto build4 = [&](int st, uint32_t* dst) {
            int d0 = i0 - st;
            int rem0 = d0;
            if (d0 >= 0) {
                unsigned u = (unsigned)d0;
                rem0 = (int)(u - ((u * M) >> 22) * (unsigned)gb);  // exact, d0<2048
            }
            uint32_t hv[5];
            #pragma unroll
            for (int k = 0; k < 5; k++) {
                int d = d0 + k, t = rem0 + k;
                bool v = (d >= 0) & (d < lim) & ((t < length) | (t >= gb));
                hv[k] = v ? 0x3C00u : 0u;          // half(1.0) bits
            }
            #pragma unroll
            for (int k = 0; k < 4; k++)
                dst[i0 + k] = hv[k] | (hv[k + 1] << 16);
        };
        build4(st1, s_lut);
        build4(st2, s_lut + SS);
    }
    if (threadIdx.x == 0) {
        float a = angles[b];
        s_trig[0] = cosf(a);
        s_trig[1] = sinf(a);
    }
    __syncthreads();

    const float cosv = s_trig[0];
    const float sinv = s_trig[1];
    const __half2* rowp = reinterpret_cast<const __half2*>(s_lut);
    const __half2* colp = reinterpret_cast<const __half2*>(s_lut) + SS;

    const float4* imgb4 = reinterpret_cast<const float4*>(img + (size_t)b * HH * WW * 3);
    float4*       outb4 = reinterpret_cast<float4*>(out + (size_t)b * HH * WW * 3);

    // Bilinear sample of separable mask at rotated coords.
    // Coords provably within [150,873] (radius sqrt(2)*255.5 < 511.5): no reflect.
    auto sample = [&](float sx, float sy) -> float {
        float x0f = floorf(sx), y0f = floorf(sy);
        float fx = sx - x0f,    fy = sy - y0f;
        float2 rr = __half22float2(rowp[(int)y0f]);
        float2 cc = __half22float2(colp[(int)x0f]);
        float R = fmaf(fy, rr.y - rr.x, rr.x);
        float C = fmaf(fx, cc.y - cc.x, cc.x);
        return fmaf(C, 1.0f - R, R);      // binary OR: R + C - R*C
    };

    const unsigned a0 = blockIdx.x * F4_PER_BLOCK + threadIdx.x;

    // Pixel-B deltas: normal (+1 in x) or row-wrap (x:511->0, y:+1)
    const float wdx = sinv - 511.0f * cosv;
    const float wdy = cosv + 511.0f * sinv;

    #pragma unroll
    for (int r = 0; r < NROUNDS; r++) {
        const unsigned base = a0 + r * (NTHREADS * F4_PER_ROUND);

        // Phase 1: masks first (independent per-f4 index math, delta for pixel B)
        float mA[F4_PER_ROUND], mB[F4_PER_ROUND];
        int   r3[F4_PER_ROUND];
        #pragma unroll
        for (int i = 0; i < F4_PER_ROUND; i++) {
            unsigned f0 = (base + i * NTHREADS) * 4u;
            unsigned p  = f0 / 3u;        // compiler magic-mul
            r3[i] = (int)(f0 - p * 3u);
            unsigned w = p & (WW - 1);
            float xx = (float)(int)w        - 255.5f;
            float yy = (float)(int)(p >> 9) - 255.5f;
            float sx = fmaf(cosv, xx, fmaf(sinv,  yy, 511.5f));
            float sy = fmaf(-sinv, xx, fmaf(cosv, yy, 511.5f));
            mA[i] = sample(sx, sy);
            bool wrap = (w == WW - 1);
            mB[i] = sample(sx + (wrap ? wdx : cosv),
                           sy + (wrap ? wdy : -sinv));
        }

        // Phase 2: predicated back-to-back streaming loads.
        // Exact-zero mask (~16% of area, zero cells >=61px wide) -> skip read.
        float4 v[F4_PER_ROUND];
        #pragma unroll
        for (int i = 0; i < F4_PER_ROUND; i++) {
            if (mA[i] != 0.0f || mB[i] != 0.0f)
                v[i] = __ldcs(&imgb4[base + i * NTHREADS]);
            else
                v[i] = make_float4(0.f, 0.f, 0.f, 0.f);
        }

        // Phase 3: multiply + coalesced streaming stores
        // component->pixel by f0 mod 3:
        //   0: x,y,z->A w->B ; 1: x,y->A z,w->B ; 2: x->A y,z,w->B
        #pragma unroll
        for (int i = 0; i < F4_PER_ROUND; i++) {
            float my = (r3[i] == 2) ? mB[i] : mA[i];
            float mz = (r3[i] == 0) ? mA[i] : mB[i];
            float4 o = make_float4(v[i].x * mA[i], v[i].y * my,
                                   v[i].z * mz,    v[i].w * mB[i]);
            __stcs(&outb4[base + i * NTHREADS], o);
        }
    }
}

extern "C" void kernel_launch(void* const* d_in, const int* in_sizes, int n_in,
                              void* d_out, int out_size) {
    const float* images    = (const float*)d_in[0];
    const float* angles    = (const float*)d_in[1];
    const int*   gridblock = (const int*)  d_in[2];
    const int*   start1    = (const int*)  d_in[3];
    const int*   start2    = (const int*)  d_in[4];
    float* out = (float*)d_out;

    dim3 grid(BLOCKS_X, BB);   // (96, 32)
    gridmask_kernel<<<grid, NTHREADS>>>(images, angles, gridblock, start1, start2, out);
}

// round 15
// speedup vs baseline: 1.0072x; 1.0072x over previous
#include <cuda_runtime.h>
#include <cuda_fp16.h>
#include <cstdint>

#define SS   1024
#define HH   512
#define WW   512
#define BB   32
#define NTHREADS 256
#define F4_PER_ROUND 4
#define NROUNDS 2
#define F4_PER_BLOCK (NTHREADS * F4_PER_ROUND * NROUNDS)  // 2048
#define F4_PER_IMG   (HH*WW*3/4)                          // 196608
#define BLOCKS_X     (F4_PER_IMG / F4_PER_BLOCK)          // 96

__global__ __launch_bounds__(NTHREADS, 8)
void gridmask_kernel(const float* __restrict__ img,
                     const float* __restrict__ angles,
                     const int*   __restrict__ gridblock,
                     const int*   __restrict__ start1,
                     const int*   __restrict__ start2,
                     float*       __restrict__ out) {
    // fp16 paired stripe LUTs stored as raw half2 bits:
    //   s_lut[i]      = (rowstripe(i), rowstripe(i+1))
    //   s_lut[SS + i] = (colstripe(i), colstripe(i+1))
    __shared__ uint32_t s_lut[2 * SS];   // 8 KB
    __shared__ float    s_trig[2];

    const int b = blockIdx.y;

    // ---- Branchless int-packed LUT build ----
    // stripe(d) over a 5-run: v = (d>=0) & (d<lim) & ((t<length)|(t>=gb)),
    // t = rem0+k. Valid because length>=91>4 and gb>=153>4.
    {
        const int gb  = gridblock[b];
        const int st1 = start1[b];
        const int st2 = start2[b];
        float lf = __fadd_rn(__fmul_rn((float)gb, 0.6f), 0.5f);
        int length = (int)lf;
        length = min(max(length, 1), gb - 1);
        const unsigned M = (1u << 22) / (unsigned)gb + 1u;
        const int lim = (int)((((unsigned)SS * M) >> 22) * (unsigned)gb);
        const int i0 = threadIdx.x * 4;

        auto build4 = [&](int st, uint32_t* dst) {
            int d0 = i0 - st;
            int rem0 = d0;
            if (d0 >= 0) {
                unsigned u = (unsigned)d0;
                rem0 = (int)(u - ((u * M) >> 22) * (unsigned)gb);  // exact, d0<2048
            }
            uint32_t hv[5];
            #pragma unroll
            for (int k = 0; k < 5; k++) {
                int d = d0 + k, t = rem0 + k;
                bool v = (d >= 0) & (d < lim) & ((t < length) | (t >= gb));
                hv[k] = v ? 0x3C00u : 0u;          // half(1.0) bits
            }
            #pragma unroll
            for (int k = 0; k < 4; k++)
                dst[i0 + k] = hv[k] | (hv[k + 1] << 16);
        };
        build4(st1, s_lut);
        build4(st2, s_lut + SS);
    }
    if (threadIdx.x == 0) {
        float a = angles[b];
        s_trig[0] = cosf(a);
        s_trig[1] = sinf(a);
    }
    __syncthreads();

    const float cosv = s_trig[0];
    const float sinv = s_trig[1];
    const __half2* rowp = reinterpret_cast<const __half2*>(s_lut);
    const __half2* colp = reinterpret_cast<const __half2*>(s_lut) + SS;

    const float4* imgb4 = reinterpret_cast<const float4*>(img + (size_t)b * HH * WW * 3);
    float4*       outb4 = reinterpret_cast<float4*>(out + (size_t)b * HH * WW * 3);

    // Bilinear sample of separable mask at rotated coords.
    // Coords provably within [150,873] (radius sqrt(2)*255.5 < 511.5): no reflect.
    auto sample = [&](float sx, float sy) -> float {
        float x0f = floorf(sx), y0f = floorf(sy);
        float fx = sx - x0f,    fy = sy - y0f;
        float2 rr = __half22float2(rowp[(int)y0f]);
        float2 cc = __half22float2(colp[(int)x0f]);
        float R = fmaf(fy, rr.y - rr.x, rr.x);
        float C = fmaf(fx, cc.y - cc.x, cc.x);
        return fmaf(C, 1.0f - R, R);      // binary OR: R + C - R*C
    };

    const unsigned a0 = blockIdx.x * F4_PER_BLOCK + threadIdx.x;

    // Pixel-B deltas: normal (+1 in x) or row-wrap (x:511->0, y:+1)
    const float wdx = sinv - 511.0f * cosv;
    const float wdy = cosv + 511.0f * sinv;

    #pragma unroll
    for (int r = 0; r < NROUNDS; r++) {
        const unsigned base = a0 + r * (NTHREADS * F4_PER_ROUND);

        // Phase 1: masks first (independent per-f4 index math, delta for pixel B)
        float mA[F4_PER_ROUND], mB[F4_PER_ROUND];
        int   r3[F4_PER_ROUND];
        #pragma unroll
        for (int i = 0; i < F4_PER_ROUND; i++) {
            unsigned f0 = (base + i * NTHREADS) * 4u;
            unsigned p  = f0 / 3u;        // compiler magic-mul
            r3[i] = (int)(f0 - p * 3u);
            unsigned w = p & (WW - 1);
            float xx = (float)(int)w        - 255.5f;
            float yy = (float)(int)(p >> 9) - 255.5f;
            float sx = fmaf(cosv, xx, fmaf(sinv,  yy, 511.5f));
            float sy = fmaf(-sinv, xx, fmaf(cosv, yy, 511.5f));
            mA[i] = sample(sx, sy);
            bool wrap = (w == WW - 1);
            mB[i] = sample(sx + (wrap ? wdx : cosv),
                           sy + (wrap ? wdy : -sinv));
        }

        // Phase 2: predicated back-to-back loads, L2 evict-NORMAL (__ldcg):
        // the image is re-read every graph replay and ~fits in L2; evict-first
        // (__ldcs) was flushing it and forcing ~36MB/replay back to DRAM.
        float4 v[F4_PER_ROUND];
        #pragma unroll
        for (int i = 0; i < F4_PER_ROUND; i++) {
            if (mA[i] != 0.0f || mB[i] != 0.0f)
                v[i] = __ldcg(&imgb4[base + i * NTHREADS]);
            else
                v[i] = make_float4(0.f, 0.f, 0.f, 0.f);
        }

        // Phase 3: multiply + coalesced evict-first stores (write-once stream)
        // component->pixel by f0 mod 3:
        //   0: x,y,z->A w->B ; 1: x,y->A z,w->B ; 2: x->A y,z,w->B
        #pragma unroll
        for (int i = 0; i < F4_PER_ROUND; i++) {
            float my = (r3[i] == 2) ? mB[i] : mA[i];
            float mz = (r3[i] == 0) ? mA[i] : mB[i];
            float4 o = make_float4(v[i].x * mA[i], v[i].y * my,
                                   v[i].z * mz,    v[i].w * mB[i]);
            __stcs(&outb4[base + i * NTHREADS], o);
        }
    }
}

extern "C" void kernel_launch(void* const* d_in, const int* in_sizes, int n_in,
                              void* d_out, int out_size) {
    const float* images    = (const float*)d_in[0];
    const float* angles    = (const float*)d_in[1];
    const int*   gridblock = (const int*)  d_in[2];
    const int*   start1    = (const int*)  d_in[3];
    const int*   start2    = (const int*)  d_in[4];
    float* out = (float*)d_out;

    dim3 grid(BLOCKS_X, BB);   // (96, 32)
    gridmask_kernel<<<grid, NTHREADS>>>(images, angles, gridblock, start1, start2, out);
}